// round 15
// baseline (speedup 1.0000x reference)
#include <cuda_runtime.h>

#define FULL_MASK 0xffffffffu
#define NLOG2E (-1.4426950408889634f)   // -log2(e)

// sigmoid((x)*scale) with scale/log2e/sign folded into one constant:
// sigma = 1/(1+2^(x*c)), c = -scale*log2(e). Same MUFU ops (EX2,RCP) the
// __expf/__fdividef path emits, one fewer FMUL.
__device__ __forceinline__ float sigmoid_c(float x, float c) {
    float e, r;
    asm("ex2.approx.f32 %0, %1;" : "=f"(e) : "f"(x * c));
    asm("rcp.approx.f32 %0, %1;" : "=f"(r) : "f"(1.0f + e));
    return r;
}

// padded SMEM index for the s8 transpose: conflict-free both directions
__device__ __forceinline__ int padidx(int L) { return L + (L >> 5); }

// 256-bit global load, L2 evict_last (input biased to stay L2-resident).
__device__ __forceinline__ void ldg256_evl(const float* p, float v[8]) {
    unsigned r0,r1,r2,r3,r4,r5,r6,r7;
    asm volatile("ld.global.nc.L2::evict_last.v8.b32 {%0,%1,%2,%3,%4,%5,%6,%7}, [%8];"
        : "=r"(r0),"=r"(r1),"=r"(r2),"=r"(r3),
          "=r"(r4),"=r"(r5),"=r"(r6),"=r"(r7) : "l"(p));
    v[0]=__uint_as_float(r0); v[1]=__uint_as_float(r1);
    v[2]=__uint_as_float(r2); v[3]=__uint_as_float(r3);
    v[4]=__uint_as_float(r4); v[5]=__uint_as_float(r5);
    v[6]=__uint_as_float(r6); v[7]=__uint_as_float(r7);
}
// 256-bit global store, L2 evict_first (output streams through L2).
__device__ __forceinline__ void stg256_evf(float* p, const float v[8]) {
    asm volatile("st.global.L2::evict_first.v8.b32 [%0], {%1,%2,%3,%4,%5,%6,%7,%8};"
        :: "l"(p),
           "r"(__float_as_uint(v[0])), "r"(__float_as_uint(v[1])),
           "r"(__float_as_uint(v[2])), "r"(__float_as_uint(v[3])),
           "r"(__float_as_uint(v[4])), "r"(__float_as_uint(v[5])),
           "r"(__float_as_uint(v[6])), "r"(__float_as_uint(v[7]))
        : "memory");
}

// One warp per row of 1024 floats, complete binary tree depth 10.
// Chunk M (0..127) = aligned 8-leaf block = a d=7 subtree.
// Phase A (coalesced, M = lane+32k): 256-bit load; ALL per-chunk diffs
//   (d7 scalar, d8 float2, d9 float4) parked in per-warp SMEM (reg relief),
//   chunk sums s8 staged through padded SMEM to switch ownership.
// Phase B (lane t owns chunks 4t..4t+3 = leaves [32t,32t+32)): within-lane
//   tree (d=5,6) + 5-step shfl butterfly (d=0..4); path probs p8 staged back.
// Phase C (coalesced): finish levels d=7,8,9 from SMEM diffs, 256-bit store.
__global__ void __launch_bounds__(256, 6)
nbdt_kernel(const float* __restrict__ in, float* __restrict__ out)
{
    __shared__ float  s8s[8][132 + 128];  // [0,132): s8/p8 padded; [132,260): d7
    __shared__ float4 d9s[8][128];        // leaf-pair diffs
    __shared__ float2 d8s[8][128];        // 2-leaf-block diffs
    const int warp = threadIdx.x >> 5;
    const int lane = threadIdx.x & 31;
    const int row  = (blockIdx.x << 3) + warp;

    const float* rin  = in  + (size_t)row * 1024;
    float*       rout = out + (size_t)row * 1024;

    // ---- Phase A ----
    #pragma unroll
    for (int k = 0; k < 4; k++) {
        int M = lane + (k << 5);
        float v[8];
        ldg256_evl(rin + (M << 3), v);
        float a0 = v[0]+v[1], a1 = v[2]+v[3], a2 = v[4]+v[5], a3 = v[6]+v[7];
        d9s[warp][M] = make_float4(v[0]-v[1], v[2]-v[3], v[4]-v[5], v[6]-v[7]);
        float b0 = a0 + a1, b1 = a2 + a3;
        d8s[warp][M] = make_float2(a0 - a1, a2 - a3);
        s8s[warp][132 + M] = b0 - b1;          // d7, same-lane slot
        s8s[warp][padidx(M)] = b0 + b1;        // s8 -> transpose
    }
    __syncwarp();

    // ---- Phase B ----
    float s8[4];
    #pragma unroll
    for (int j = 0; j < 4; j++)
        s8[j] = s8s[warp][padidx((lane << 2) + j)];
    float s16[2] = { s8[0] + s8[1], s8[2] + s8[3] };
    float sum = s16[0] + s16[1];               // sum of my 32 leaves

    // cross-lane levels d=4..0: prob = sigmoid((my_sum - sib_sum)/blk),
    // blk doubles each step going UP the tree -> constant HALVES each step.
    float acc = 1.0f;
    float c = NLOG2E / 32.0f;
    #pragma unroll
    for (int s = 0; s < 5; s++) {
        float part = __shfl_xor_sync(FULL_MASK, sum, 1 << s);
        acc *= sigmoid_c(sum - part, c);
        sum += part;
        c *= 0.5f;
    }

    // d=5 (16-leaf children)
    float p16[2];
    {
        float pl = sigmoid_c(s16[0] - s16[1], NLOG2E / 16.0f);
        float a = acc * pl;  p16[0] = a;  p16[1] = acc - a;
    }
    // d=6 (8-leaf children) -> per-chunk path prob p8, staged back.
    // Same-lane slots: no cross-lane sync needed before these writes.
    #pragma unroll
    for (int i = 0; i < 2; i++) {
        float pl = sigmoid_c(s8[2*i] - s8[2*i+1], NLOG2E / 8.0f);
        float a = p16[i] * pl;
        s8s[warp][padidx((lane << 2) + 2*i)]     = a;
        s8s[warp][padidx((lane << 2) + 2*i + 1)] = p16[i] - a;
    }
    __syncwarp();

    // ---- Phase C ----
    #pragma unroll
    for (int k = 0; k < 4; k++) {
        int M = lane + (k << 5);
        float p   = s8s[warp][padidx(M)];
        float pl7 = sigmoid_c(s8s[warp][132 + M], NLOG2E / 4.0f);
        float hi = p * pl7, lo = p - hi;
        float2 d8 = d8s[warp][M];
        float pa = sigmoid_c(d8.x, NLOG2E / 2.0f);
        float q0 = hi * pa, q1 = hi - q0;
        float pb = sigmoid_c(d8.y, NLOG2E / 2.0f);
        float q2 = lo * pb, q3 = lo - q2;
        float4 d9 = d9s[warp][M];
        float o[8];
        float t0 = sigmoid_c(d9.x, NLOG2E); o[0] = q0 * t0; o[1] = q0 - o[0];
        float t1 = sigmoid_c(d9.y, NLOG2E); o[2] = q1 * t1; o[3] = q1 - o[2];
        float t2 = sigmoid_c(d9.z, NLOG2E); o[4] = q2 * t2; o[5] = q2 - o[4];
        float t3 = sigmoid_c(d9.w, NLOG2E); o[6] = q3 * t3; o[7] = q3 - o[6];
        stg256_evf(rout + (M << 3), o);
    }
}

extern "C" void kernel_launch(void* const* d_in, const int* in_sizes, int n_in,
                              void* d_out, int out_size)
{
    const float* in = (const float*)d_in[0];
    float* out = (float*)d_out;
    int rows = in_sizes[0] / 1024;             // BATCH = 16384
    nbdt_kernel<<<rows / 8, 256>>>(in, out);
}